// round 8
// baseline (speedup 1.0000x reference)
#include <cuda_runtime.h>
#include <cuda_fp16.h>
#include <math_constants.h>
#include <cstdint>

#define B_  4
#define N_  4096
#define C_  256
#define NT_ 64   // key tiles of 64
#define NP_ 320  // packed projection cols: 32 f + 32 g(pre-scaled by log2e) + 256 h

// ---------------------------------------------------------------------------
// Scratch (__device__ globals; allocation-free rule)
// ---------------------------------------------------------------------------
__device__ uint4 g_xs[B_ * N_ * 64];          // x split fp16 [BN][256hi|256lo]
__device__ uint4 g_wt[NP_ * 64];              // W^T split fp16 [320][256hi|256lo]
__device__ float g_pb[NP_];                   // packed bias
__device__ uint4 g_fs[B_ * N_ * 8];           // F split fp16 [B,N,(32hi|32lo)]
__device__ uint4 g_gs[B_ * N_ * 8];           // G split fp16 [B,N,(32hi|32lo)]
__device__ uint4 g_ht[B_ * C_ * N_ / 8];      // H^T fp16 [B,C,N]

// ---------------------------------------------------------------------------
// Helpers
// ---------------------------------------------------------------------------
__device__ __forceinline__ uint32_t smem_u32(const void* p) {
    uint32_t a;
    asm("{ .reg .u64 t; cvta.to.shared.u64 t, %1; cvt.u32.u64 %0, t; }" : "=r"(a) : "l"(p));
    return a;
}
__device__ __forceinline__ void ldsm4(uint32_t* r, uint32_t addr) {
    asm volatile("ldmatrix.sync.aligned.m8n8.x4.shared.b16 {%0,%1,%2,%3}, [%4];"
        : "=r"(r[0]), "=r"(r[1]), "=r"(r[2]), "=r"(r[3]) : "r"(addr));
}
__device__ __forceinline__ void mma_f16(float* d, const uint32_t* a, uint32_t b0, uint32_t b1) {
    asm volatile("mma.sync.aligned.m16n8k16.row.col.f32.f16.f16.f32 "
        "{%0,%1,%2,%3}, {%4,%5,%6,%7}, {%8,%9}, {%0,%1,%2,%3};"
        : "+f"(d[0]), "+f"(d[1]), "+f"(d[2]), "+f"(d[3])
        : "r"(a[0]), "r"(a[1]), "r"(a[2]), "r"(a[3]), "r"(b0), "r"(b1));
}
__device__ __forceinline__ void cp16(uint32_t dst, const void* src) {
    asm volatile("cp.async.cg.shared.global [%0], [%1], 16;" :: "r"(dst), "l"(src) : "memory");
}
__device__ __forceinline__ float ex2(float x) {
    float y; asm("ex2.approx.f32 %0, %1;" : "=f"(y) : "f"(x)); return y;
}
#define CP_COMMIT()  asm volatile("cp.async.commit_group;" ::: "memory")
#define CP_WAIT(n)   asm volatile("cp.async.wait_group %0;" :: "n"(n) : "memory")

// ---------------------------------------------------------------------------
// prep_x: x fp32 [BN,256] -> xs fp16 [BN][256hi|256lo]
// ---------------------------------------------------------------------------
__global__ __launch_bounds__(256) void prep_x(const float* __restrict__ x, uint4* __restrict__ xs)
{
    int id = blockIdx.x * 256 + threadIdx.x;
    int r = id >> 5, c = id & 31;
    const float4* src = (const float4*)(x + (long)r * 256 + c * 8);
    float4 v0 = src[0], v1 = src[1];
    float vv[8] = {v0.x, v0.y, v0.z, v0.w, v1.x, v1.y, v1.z, v1.w};
    __half hv[8], lv[8];
#pragma unroll
    for (int i = 0; i < 8; i++) {
        hv[i] = __float2half_rn(vv[i]);
        lv[i] = __float2half_rn(vv[i] - __half2float(hv[i]));
    }
    xs[(long)r * 64 + c]      = *(uint4*)hv;
    xs[(long)r * 64 + 32 + c] = *(uint4*)lv;
}

// ---------------------------------------------------------------------------
// prep_w: pack [Wf|Wg*log2e|Wh]^T fp16 hi/lo + bias.  g pre-scaled so the
// attention softmax can use ex2 directly (exp(s) = 2^(s*log2e)).
// ---------------------------------------------------------------------------
__global__ __launch_bounds__(256) void prep_w(
    const float* __restrict__ Wf, const float* __restrict__ Wg, const float* __restrict__ Wh,
    const float* __restrict__ bf, const float* __restrict__ bg, const float* __restrict__ bh,
    __half* __restrict__ wt, float* __restrict__ pb)
{
    const float L2E = 1.4426950408889634f;
    int n = blockIdx.x, k = threadIdx.x;
    float w = (n < 32) ? Wf[k * 32 + n]
            : (n < 64) ? Wg[k * 32 + (n - 32)] * L2E
                       : Wh[k * 256 + (n - 64)];
    __half hv = __float2half_rn(w);
    __half lv = __float2half_rn(w - __half2float(hv));
    wt[(long)n * 512 + k] = hv;
    wt[(long)n * 512 + 256 + k] = lv;
    if (k == 0)
        pb[n] = (n < 32) ? bf[n] : (n < 64) ? bg[n - 32] * L2E : bh[n - 64];
}

// ---------------------------------------------------------------------------
// Fused projection GEMM + transposed h epilogue.
// Block 128x64, 8 warps (4m x 2n).  blockIdx.x==0 -> f/g hi/lo split output;
// blockIdx.x>=1 -> h written TRANSPOSED to ht[B,C,N] via smem staging.
// ---------------------------------------------------------------------------
#define PG_STAGE 49152
#define PG_SMEM  (2 * PG_STAGE + 256)

__global__ __launch_bounds__(256) void proj_mma(
    const uint4* __restrict__ xs, const uint4* __restrict__ wt,
    const float* __restrict__ pb,
    __half* __restrict__ fsh, __half* __restrict__ gsh, __half* __restrict__ ht)
{
    extern __shared__ char smem[];
    const uint32_t sb = smem_u32(smem);
    float* sbias = (float*)(smem + 2 * PG_STAGE);
    const int tid = threadIdx.x, lane = tid & 31, wid = tid >> 5;
    const int wm = wid & 3, wn = wid >> 2;
    const int n0 = blockIdx.x * 64, m0 = blockIdx.y * 128;

    const int la_row = (((lane >> 3) & 1) << 3) | (lane & 7);
    const int la_sel = lane >> 4;
    const int lb_row = ((lane >> 4) << 3) | (lane & 7);
    const int lb_sel = (lane >> 3) & 1;

    if (tid < 64) sbias[tid] = pb[n0 + tid];

    auto issue_stage = [&](int kt, int st) {
        uint32_t base = sb + st * PG_STAGE;
#pragma unroll
        for (int i = 0; i < 4; i++) {
            int idx = tid + i * 256;
            int r = idx >> 3, c = idx & 7;
            uint32_t sw = ((c ^ (r & 7)) << 4);
            cp16(base + r * 128 + sw,          xs + (long)(m0 + r) * 64 + kt * 8 + c);
            cp16(base + 16384 + r * 128 + sw,  xs + (long)(m0 + r) * 64 + 32 + kt * 8 + c);
        }
#pragma unroll
        for (int i = 0; i < 2; i++) {
            int idx = tid + i * 256;
            int r = idx >> 3, c = idx & 7;
            uint32_t sw = ((c ^ (r & 7)) << 4);
            cp16(base + 32768 + r * 128 + sw,        wt + (long)(n0 + r) * 64 + kt * 8 + c);
            cp16(base + 32768 + 8192 + r * 128 + sw, wt + (long)(n0 + r) * 64 + 32 + kt * 8 + c);
        }
        CP_COMMIT();
    };

    issue_stage(0, 0);

    float d[2][4][4];
#pragma unroll
    for (int mh = 0; mh < 2; mh++)
#pragma unroll
        for (int i = 0; i < 4; i++)
#pragma unroll
            for (int j = 0; j < 4; j++) d[mh][i][j] = 0.f;

#pragma unroll 1
    for (int kt = 0; kt < 4; kt++) {
        if (kt < 3) { issue_stage(kt + 1, (kt + 1) & 1); CP_WAIT(1); }
        else        { CP_WAIT(0); }
        __syncthreads();
        uint32_t buf = sb + (kt & 1) * PG_STAGE;

#pragma unroll
        for (int kc = 0; kc < 4; kc++) {
            uint32_t ah[2][4], al[2][4], bh[2][4], bl[2][4];
#pragma unroll
            for (int mh = 0; mh < 2; mh++) {
                int arow = wm * 32 + mh * 16 + la_row;
                uint32_t sw = (((2 * kc + la_sel) ^ (arow & 7)) << 4);
                ldsm4(ah[mh], buf + arow * 128 + sw);
                ldsm4(al[mh], buf + 16384 + arow * 128 + sw);
            }
#pragma unroll
            for (int n16 = 0; n16 < 2; n16++) {
                int brow = wn * 32 + n16 * 16 + lb_row;
                uint32_t sw = (((2 * kc + lb_sel) ^ (brow & 7)) << 4);
                ldsm4(bh[n16], buf + 32768 + brow * 128 + sw);
                ldsm4(bl[n16], buf + 32768 + 8192 + brow * 128 + sw);
            }
#pragma unroll
            for (int mh = 0; mh < 2; mh++)
#pragma unroll
                for (int n16 = 0; n16 < 2; n16++)
#pragma unroll
                    for (int j = 0; j < 2; j++) {
                        float* dd = d[mh][n16 * 2 + j];
                        mma_f16(dd, ah[mh], bh[n16][2 * j], bh[n16][2 * j + 1]);
                        mma_f16(dd, ah[mh], bl[n16][2 * j], bl[n16][2 * j + 1]);
                        mma_f16(dd, al[mh], bh[n16][2 * j], bh[n16][2 * j + 1]);
                    }
        }
        __syncthreads();
    }

    if (blockIdx.x == 0) {
        // ---- f/g epilogue: hi/lo split layout ----
#pragma unroll
        for (int mh = 0; mh < 2; mh++) {
            const long mrow0 = m0 + wm * 32 + mh * 16 + (lane >> 2);
            const long mrow1 = mrow0 + 8;
#pragma unroll
            for (int n16 = 0; n16 < 2; n16++)
#pragma unroll
                for (int j = 0; j < 2; j++) {
                    const float* dd = d[mh][n16 * 2 + j];
                    int col = wn * 32 + n16 * 16 + j * 8 + (lane & 3) * 2;
                    float b0 = sbias[col], b1 = sbias[col + 1];
                    float v00 = dd[0] + b0, v01 = dd[1] + b1;
                    float v10 = dd[2] + b0, v11 = dd[3] + b1;
                    __half* dst = (col < 32) ? fsh : gsh;
                    int c = col & 31;
                    __half2 h0 = __floats2half2_rn(v00, v01);
                    float2 f0 = __half22float2(h0);
                    __half2 l0 = __floats2half2_rn(v00 - f0.x, v01 - f0.y);
                    *(__half2*)(dst + mrow0 * 64 + c) = h0;
                    *(__half2*)(dst + mrow0 * 64 + 32 + c) = l0;
                    __half2 h1 = __floats2half2_rn(v10, v11);
                    float2 f1 = __half22float2(h1);
                    __half2 l1 = __floats2half2_rn(v10 - f1.x, v11 - f1.y);
                    *(__half2*)(dst + mrow1 * 64 + c) = h1;
                    *(__half2*)(dst + mrow1 * 64 + 32 + c) = l1;
                }
        }
    } else {
        // ---- h epilogue: transpose via smem, write ht[B,C,N] coalesced ----
        __half* sT = (__half*)smem;            // [64 ch][136 stride]
#pragma unroll
        for (int mh = 0; mh < 2; mh++) {
            const int r0 = wm * 32 + mh * 16 + (lane >> 2);
            const int r1 = r0 + 8;
#pragma unroll
            for (int n16 = 0; n16 < 2; n16++)
#pragma unroll
                for (int j = 0; j < 2; j++) {
                    const float* dd = d[mh][n16 * 2 + j];
                    int col = wn * 32 + n16 * 16 + j * 8 + (lane & 3) * 2;
                    float b0 = sbias[col], b1 = sbias[col + 1];
                    sT[col * 136 + r0]       = __float2half_rn(dd[0] + b0);
                    sT[(col + 1) * 136 + r0] = __float2half_rn(dd[1] + b1);
                    sT[col * 136 + r1]       = __float2half_rn(dd[2] + b0);
                    sT[(col + 1) * 136 + r1] = __float2half_rn(dd[3] + b1);
                }
        }
        __syncthreads();
        const int b = m0 >> 12;                // m0 / N_
        const int noff = m0 & (N_ - 1);
        const int ch = tid >> 2, q = tid & 3;
        uint4* dst = (uint4*)(ht + ((long)b * C_ + (n0 - 64) + ch) * N_ + noff + q * 32);
        const uint4* srcp = (const uint4*)(sT + ch * 136 + q * 32);
#pragma unroll
        for (int i = 0; i < 4; i++) dst[i] = srcp[i];
    }
}

// ---------------------------------------------------------------------------
// Attention: block = 128 q-rows x batch. 8 warps, one m16 row-slice each.
// Software-pipelined: iter t issues MMA1(t), MMA2(t-1), then softmax(t)
// (MUFU/ALU overlaps the draining tensor work).  4-stage cp.async ring.
// Softmax in log2 domain (G pre-scaled by log2e) -> raw ex2.
// ---------------------------------------------------------------------------
#define OFF_SG     0
#define STAGE_SZ   (8192 + 32768)
#define OFF_SF(s)  (16384 + (s) * STAGE_SZ)
#define OFF_SH(s)  (16384 + (s) * STAGE_SZ + 8192)
#define SMEM_TOTAL (16384 + 4 * STAGE_SZ)    // 176 KB

__global__ __launch_bounds__(256, 1) void attn_mma(
    const uint4* __restrict__ fsplit, const uint4* __restrict__ gsplit,
    const uint4* __restrict__ ht4,
    const float* __restrict__ x, const float* __restrict__ gamma, float* __restrict__ y)
{
    extern __shared__ char smem[];
    const uint32_t sb = smem_u32(smem);
    const int tid = threadIdx.x, lane = tid & 31, wid = tid >> 5;
    const int b = blockIdx.y, q0 = blockIdx.x * 128;

    const int la_row = (((lane >> 3) & 1) << 3) | (lane & 7);
    const int la_sel = lane >> 4;
    const int lb_row = ((lane >> 4) << 3) | (lane & 7);
    const int lb_sel = (lane >> 3) & 1;

    const int hr = tid >> 3, hc = tid & 7;
    const long hbase = (long)b * C_ * (N_ / 8);
    const long fbase = (long)b * N_ * 8;

    auto stage_attn = [&](int t) {
        const int sn = t & 3;
#pragma unroll
        for (int i = 0; i < 2; i++) {
            int idx = tid + i * 256;
            int r = idx >> 3, c = idx & 7;
            cp16(sb + OFF_SF(sn) + r * 128 + (((c) ^ (r & 7)) << 4),
                 fsplit + fbase + (long)(t * 64 + r) * 8 + c);
        }
#pragma unroll
        for (int i = 0; i < 8; i++) {
            int r = hr + i * 32;
            cp16(sb + OFF_SH(sn) + r * 128 + (((hc) ^ (r & 7)) << 4),
                 ht4 + hbase + (long)r * (N_ / 8) + t * 8 + hc);
        }
    };

    // ---- load G tile [128 rows x 128B], swizzled ----
#pragma unroll
    for (int i = 0; i < 4; i++) {
        int idx = tid + i * 256;
        int r = idx >> 3, c = idx & 7;
        uint4 v = gsplit[(long)(b * N_ + q0 + r) * 8 + c];
        *(uint4*)(smem + OFF_SG + r * 128 + (((c) ^ (r & 7)) << 4)) = v;
    }

    // ---- prologue: issue stages 0 and 1 ----
    stage_attn(0); CP_COMMIT();
    stage_attn(1); CP_COMMIT();

    // ---- hoist G A-fragments (constant over tiles) ----
    __syncthreads();
    uint32_t gh[2][4], gl[2][4];
    {
        int row = wid * 16 + la_row;
        uint32_t rowoff = sb + OFF_SG + row * 128;
#pragma unroll
        for (int kc = 0; kc < 2; kc++) {
            ldsm4(gh[kc], rowoff + ((((2 * kc) + la_sel) ^ (row & 7)) << 4));
            ldsm4(gl[kc], rowoff + ((((4 + 2 * kc) + la_sel) ^ (row & 7)) << 4));
        }
    }

    float o[32][4];
#pragma unroll
    for (int i = 0; i < 32; i++)
#pragma unroll
        for (int j = 0; j < 4; j++) o[i][j] = 0.f;
    float lsum0 = 0.f, lsum1 = 0.f;
    float mrun0 = -CUDART_INF_F, mrun1 = -CUDART_INF_F;
    uint32_t phi[16];

#pragma unroll 1
    for (int t = 0; t < NT_; t++) {
        CP_WAIT(1);
        __syncthreads();

        // ---- MMA1(t): S[16x64] in log2 domain, 3-term ----
        float sv[8][4];
#pragma unroll
        for (int i = 0; i < 8; i++)
#pragma unroll
            for (int j = 0; j < 4; j++) sv[i][j] = 0.f;

        {
            const uint32_t sfb = sb + OFF_SF(t & 3);
#pragma unroll
            for (int n16 = 0; n16 < 4; n16++) {
                int row = n16 * 16 + lb_row;
                uint32_t rowoff = sfb + row * 128;
                uint32_t fh0[4], fh1[4], fl0[4], fl1[4];
                ldsm4(fh0, rowoff + (((0 + lb_sel) ^ (row & 7)) << 4));
                ldsm4(fh1, rowoff + (((2 + lb_sel) ^ (row & 7)) << 4));
                ldsm4(fl0, rowoff + (((4 + lb_sel) ^ (row & 7)) << 4));
                ldsm4(fl1, rowoff + (((6 + lb_sel) ^ (row & 7)) << 4));
#pragma unroll
                for (int j = 0; j < 2; j++) {
                    float* sd = sv[n16 * 2 + j];
                    mma_f16(sd, gh[0], fh0[2 * j], fh0[2 * j + 1]);
                    mma_f16(sd, gh[1], fh1[2 * j], fh1[2 * j + 1]);
                    mma_f16(sd, gh[0], fl0[2 * j], fl0[2 * j + 1]);
                    mma_f16(sd, gh[1], fl1[2 * j], fl1[2 * j + 1]);
                    mma_f16(sd, gl[0], fh0[2 * j], fh0[2 * j + 1]);
                    mma_f16(sd, gl[1], fh1[2 * j], fh1[2 * j + 1]);
                }
            }
        }

        // ---- MMA2(t-1): O += P(t-1) . Ht(t-1)  (independent of MMA1 above) ----
        if (t > 0) {
            const uint32_t shb = sb + OFF_SH((t - 1) & 3);
#pragma unroll
            for (int n16 = 0; n16 < 16; n16++) {
                int row = n16 * 16 + lb_row;
                uint32_t rhoff = shb + row * 128;
#pragma unroll
                for (int kc = 0; kc < 4; kc++) {
                    uint32_t bh[4];
                    ldsm4(bh, rhoff + ((((2 * kc) + lb_sel) ^ (row & 7)) << 4));
#pragma unroll
                    for (int j = 0; j < 2; j++)
                        mma_f16(o[n16 * 2 + j], &phi[kc * 4], bh[2 * j], bh[2 * j + 1]);
                }
            }
        }

        // ---- prefetch stage t+2 (slot (t+2)&3 was last read at iter t-1) ----
        if (t + 2 < NT_) stage_attn(t + 2);
        CP_COMMIT();

        // ---- softmax(t): issues on ALU/MUFU while tensor pipe drains ----
        float mt0 = -CUDART_INF_F, mt1 = -CUDART_INF_F;
#pragma unroll
        for (int i = 0; i < 8; i++) {
            mt0 = fmaxf(mt0, fmaxf(sv[i][0], sv[i][1]));
            mt1 = fmaxf(mt1, fmaxf(sv[i][2], sv[i][3]));
        }
        mt0 = fmaxf(mt0, __shfl_xor_sync(0xFFFFFFFFu, mt0, 1));
        mt0 = fmaxf(mt0, __shfl_xor_sync(0xFFFFFFFFu, mt0, 2));
        mt1 = fmaxf(mt1, __shfl_xor_sync(0xFFFFFFFFu, mt1, 1));
        mt1 = fmaxf(mt1, __shfl_xor_sync(0xFFFFFFFFu, mt1, 2));

        const float mn0 = fmaxf(mrun0, mt0);
        const float mn1 = fmaxf(mrun1, mt1);
        const float a0 = ex2(mrun0 - mn0);   // 0 on first tile
        const float a1 = ex2(mrun1 - mn1);
        mrun0 = mn0; mrun1 = mn1;
        lsum0 *= a0; lsum1 *= a1;
        if (a0 != 1.f) {
#pragma unroll
            for (int i = 0; i < 32; i++) { o[i][0] *= a0; o[i][1] *= a0; }
        }
        if (a1 != 1.f) {
#pragma unroll
            for (int i = 0; i < 32; i++) { o[i][2] *= a1; o[i][3] *= a1; }
        }

#pragma unroll
        for (int kc = 0; kc < 4; kc++) {
#pragma unroll
            for (int half = 0; half < 2; half++) {
                float* sd = sv[2 * kc + half];
                float p0 = ex2(sd[0] - mn0);
                float p1 = ex2(sd[1] - mn0);
                float p2 = ex2(sd[2] - mn1);
                float p3 = ex2(sd[3] - mn1);
                lsum0 += p0 + p1;
                lsum1 += p2 + p3;
                __half2 h01 = __floats2half2_rn(p0, p1);
                __half2 h23 = __floats2half2_rn(p2, p3);
                phi[kc * 4 + half * 2 + 0] = *(uint32_t*)&h01;
                phi[kc * 4 + half * 2 + 1] = *(uint32_t*)&h23;
            }
        }
    }

    // ---- final MMA2(NT-1) ----
    {
        const uint32_t shb = sb + OFF_SH((NT_ - 1) & 3);
#pragma unroll
        for (int n16 = 0; n16 < 16; n16++) {
            int row = n16 * 16 + lb_row;
            uint32_t rhoff = shb + row * 128;
#pragma unroll
            for (int kc = 0; kc < 4; kc++) {
                uint32_t bh[4];
                ldsm4(bh, rhoff + ((((2 * kc) + lb_sel) ^ (row & 7)) << 4));
#pragma unroll
                for (int j = 0; j < 2; j++)
                    mma_f16(o[n16 * 2 + j], &phi[kc * 4], bh[2 * j], bh[2 * j + 1]);
            }
        }
    }

    // ---- reduce l over the 4 lanes sharing a row ----
    lsum0 += __shfl_xor_sync(0xFFFFFFFFu, lsum0, 1);
    lsum0 += __shfl_xor_sync(0xFFFFFFFFu, lsum0, 2);
    lsum1 += __shfl_xor_sync(0xFFFFFFFFu, lsum1, 1);
    lsum1 += __shfl_xor_sync(0xFFFFFFFFu, lsum1, 2);
    const float inv0 = 1.f / lsum0, inv1 = 1.f / lsum1;
    const float gam = gamma[0];

    // ---- epilogue: y = gamma * O/l + x ----
    const long row0g = ((long)b * N_ + q0 + wid * 16 + (lane >> 2)) * C_;
    const long row1g = row0g + 8 * C_;
#pragma unroll
    for (int n16 = 0; n16 < 16; n16++) {
#pragma unroll
        for (int j = 0; j < 2; j++) {
            const float* od = o[n16 * 2 + j];
            int ch = n16 * 16 + j * 8 + (lane & 3) * 2;
            float2 xv = *(const float2*)(x + row0g + ch);
            float2 yv;
            yv.x = fmaf(gam, od[0] * inv0, xv.x);
            yv.y = fmaf(gam, od[1] * inv0, xv.y);
            *(float2*)(y + row0g + ch) = yv;
            xv = *(const float2*)(x + row1g + ch);
            yv.x = fmaf(gam, od[2] * inv1, xv.x);
            yv.y = fmaf(gam, od[3] * inv1, xv.y);
            *(float2*)(y + row1g + ch) = yv;
        }
    }
}

// ---------------------------------------------------------------------------
extern "C" void kernel_launch(void* const* d_in, const int* in_sizes, int n_in,
                              void* d_out, int out_size)
{
    const float* x     = (const float*)d_in[0];
    const float* Wf    = (const float*)d_in[1];
    const float* bf    = (const float*)d_in[2];
    const float* Wg    = (const float*)d_in[3];
    const float* bg    = (const float*)d_in[4];
    const float* Wh    = (const float*)d_in[5];
    const float* bh    = (const float*)d_in[6];
    const float* gamma = (const float*)d_in[7];
    float* y = (float*)d_out;

    void *xs, *wt, *pb, *fs, *gs, *ht;
    cudaGetSymbolAddress(&xs, g_xs);
    cudaGetSymbolAddress(&wt, g_wt);
    cudaGetSymbolAddress(&pb, g_pb);
    cudaGetSymbolAddress(&fs, g_fs);
    cudaGetSymbolAddress(&gs, g_gs);
    cudaGetSymbolAddress(&ht, g_ht);

    const int M = B_ * N_;

    prep_x<<<M * 32 / 256, 256>>>(x, (uint4*)xs);
    prep_w<<<NP_, 256>>>(Wf, Wg, Wh, bf, bg, bh, (__half*)wt, (float*)pb);

    cudaFuncSetAttribute(proj_mma, cudaFuncAttributeMaxDynamicSharedMemorySize, PG_SMEM);
    proj_mma<<<dim3(NP_ / 64, M / 128), 256, PG_SMEM>>>(
        (const uint4*)xs, (const uint4*)wt, (const float*)pb,
        (__half*)fs, (__half*)gs, (__half*)ht);

    cudaFuncSetAttribute(attn_mma, cudaFuncAttributeMaxDynamicSharedMemorySize, SMEM_TOTAL);
    attn_mma<<<dim3(N_ / 128, B_), 256, SMEM_TOTAL>>>(
        (const uint4*)fs, (const uint4*)gs, (const uint4*)ht, x, gamma, y);
}

// round 9
// speedup vs baseline: 1.0383x; 1.0383x over previous
#include <cuda_runtime.h>
#include <cuda_fp16.h>
#include <math_constants.h>
#include <cstdint>

#define B_  4
#define N_  4096
#define C_  256
#define NT_ 64   // key tiles of 64
#define NP_ 320  // packed projection cols: 32 f + 32 g(pre-scaled by log2e) + 256 h

// ---------------------------------------------------------------------------
// Scratch (__device__ globals; allocation-free rule)
// ---------------------------------------------------------------------------
__device__ uint4 g_xs[B_ * N_ * 64];          // x split fp16 [BN][256hi|256lo]
__device__ uint4 g_wt[NP_ * 64];              // W^T split fp16 [320][256hi|256lo]
__device__ float g_pb[NP_];                   // packed bias
__device__ uint4 g_fs[B_ * N_ * 8];           // F split fp16 [B,N,(32hi|32lo)]
__device__ uint4 g_gs[B_ * N_ * 8];           // G split fp16 [B,N,(32hi|32lo)]
__device__ uint4 g_ht[B_ * C_ * N_ / 8];      // H^T fp16 [B,C,N]

// ---------------------------------------------------------------------------
// Helpers
// ---------------------------------------------------------------------------
__device__ __forceinline__ uint32_t smem_u32(const void* p) {
    uint32_t a;
    asm("{ .reg .u64 t; cvta.to.shared.u64 t, %1; cvt.u32.u64 %0, t; }" : "=r"(a) : "l"(p));
    return a;
}
__device__ __forceinline__ void ldsm4(uint32_t* r, uint32_t addr) {
    asm volatile("ldmatrix.sync.aligned.m8n8.x4.shared.b16 {%0,%1,%2,%3}, [%4];"
        : "=r"(r[0]), "=r"(r[1]), "=r"(r[2]), "=r"(r[3]) : "r"(addr));
}
__device__ __forceinline__ void mma_f16(float* d, const uint32_t* a, uint32_t b0, uint32_t b1) {
    asm volatile("mma.sync.aligned.m16n8k16.row.col.f32.f16.f16.f32 "
        "{%0,%1,%2,%3}, {%4,%5,%6,%7}, {%8,%9}, {%0,%1,%2,%3};"
        : "+f"(d[0]), "+f"(d[1]), "+f"(d[2]), "+f"(d[3])
        : "r"(a[0]), "r"(a[1]), "r"(a[2]), "r"(a[3]), "r"(b0), "r"(b1));
}
__device__ __forceinline__ void cp16(uint32_t dst, const void* src) {
    asm volatile("cp.async.cg.shared.global [%0], [%1], 16;" :: "r"(dst), "l"(src) : "memory");
}
__device__ __forceinline__ float ex2(float x) {
    float y; asm("ex2.approx.f32 %0, %1;" : "=f"(y) : "f"(x)); return y;
}
#define CP_COMMIT()  asm volatile("cp.async.commit_group;" ::: "memory")
#define CP_WAIT(n)   asm volatile("cp.async.wait_group %0;" :: "n"(n) : "memory")

// ---------------------------------------------------------------------------
// prep_x: x fp32 [BN,256] -> xs fp16 [BN][256hi|256lo]
// ---------------------------------------------------------------------------
__global__ __launch_bounds__(256) void prep_x(const float* __restrict__ x, uint4* __restrict__ xs)
{
    int id = blockIdx.x * 256 + threadIdx.x;
    int r = id >> 5, c = id & 31;
    const float4* src = (const float4*)(x + (long)r * 256 + c * 8);
    float4 v0 = src[0], v1 = src[1];
    float vv[8] = {v0.x, v0.y, v0.z, v0.w, v1.x, v1.y, v1.z, v1.w};
    __half hv[8], lv[8];
#pragma unroll
    for (int i = 0; i < 8; i++) {
        hv[i] = __float2half_rn(vv[i]);
        lv[i] = __float2half_rn(vv[i] - __half2float(hv[i]));
    }
    xs[(long)r * 64 + c]      = *(uint4*)hv;
    xs[(long)r * 64 + 32 + c] = *(uint4*)lv;
}

// ---------------------------------------------------------------------------
// prep_w: pack [Wf|Wg*log2e|Wh]^T fp16 hi/lo + bias.  g pre-scaled so the
// attention softmax can use ex2 directly (exp(s) = 2^(s*log2e)).
// ---------------------------------------------------------------------------
__global__ __launch_bounds__(256) void prep_w(
    const float* __restrict__ Wf, const float* __restrict__ Wg, const float* __restrict__ Wh,
    const float* __restrict__ bf, const float* __restrict__ bg, const float* __restrict__ bh,
    __half* __restrict__ wt, float* __restrict__ pb)
{
    const float L2E = 1.4426950408889634f;
    int n = blockIdx.x, k = threadIdx.x;
    float w = (n < 32) ? Wf[k * 32 + n]
            : (n < 64) ? Wg[k * 32 + (n - 32)] * L2E
                       : Wh[k * 256 + (n - 64)];
    __half hv = __float2half_rn(w);
    __half lv = __float2half_rn(w - __half2float(hv));
    wt[(long)n * 512 + k] = hv;
    wt[(long)n * 512 + 256 + k] = lv;
    if (k == 0)
        pb[n] = (n < 32) ? bf[n] : (n < 64) ? bg[n - 32] * L2E : bh[n - 64];
}

// ---------------------------------------------------------------------------
// Fused projection GEMM + transposed h epilogue.
// Block 128x64, 8 warps (4m x 2n).  blockIdx.x==0 -> f/g hi/lo split output;
// blockIdx.x>=1 -> h written TRANSPOSED to ht[B,C,N] via smem staging.
// ---------------------------------------------------------------------------
#define PG_STAGE 49152
#define PG_SMEM  (2 * PG_STAGE + 256)

__global__ __launch_bounds__(256) void proj_mma(
    const uint4* __restrict__ xs, const uint4* __restrict__ wt,
    const float* __restrict__ pb,
    __half* __restrict__ fsh, __half* __restrict__ gsh, __half* __restrict__ ht)
{
    extern __shared__ char smem[];
    const uint32_t sb = smem_u32(smem);
    float* sbias = (float*)(smem + 2 * PG_STAGE);
    const int tid = threadIdx.x, lane = tid & 31, wid = tid >> 5;
    const int wm = wid & 3, wn = wid >> 2;
    const int n0 = blockIdx.x * 64, m0 = blockIdx.y * 128;

    const int la_row = (((lane >> 3) & 1) << 3) | (lane & 7);
    const int la_sel = lane >> 4;
    const int lb_row = ((lane >> 4) << 3) | (lane & 7);
    const int lb_sel = (lane >> 3) & 1;

    if (tid < 64) sbias[tid] = pb[n0 + tid];

    auto issue_stage = [&](int kt, int st) {
        uint32_t base = sb + st * PG_STAGE;
#pragma unroll
        for (int i = 0; i < 4; i++) {
            int idx = tid + i * 256;
            int r = idx >> 3, c = idx & 7;
            uint32_t sw = ((c ^ (r & 7)) << 4);
            cp16(base + r * 128 + sw,          xs + (long)(m0 + r) * 64 + kt * 8 + c);
            cp16(base + 16384 + r * 128 + sw,  xs + (long)(m0 + r) * 64 + 32 + kt * 8 + c);
        }
#pragma unroll
        for (int i = 0; i < 2; i++) {
            int idx = tid + i * 256;
            int r = idx >> 3, c = idx & 7;
            uint32_t sw = ((c ^ (r & 7)) << 4);
            cp16(base + 32768 + r * 128 + sw,        wt + (long)(n0 + r) * 64 + kt * 8 + c);
            cp16(base + 32768 + 8192 + r * 128 + sw, wt + (long)(n0 + r) * 64 + 32 + kt * 8 + c);
        }
        CP_COMMIT();
    };

    issue_stage(0, 0);

    float d[2][4][4];
#pragma unroll
    for (int mh = 0; mh < 2; mh++)
#pragma unroll
        for (int i = 0; i < 4; i++)
#pragma unroll
            for (int j = 0; j < 4; j++) d[mh][i][j] = 0.f;

#pragma unroll 1
    for (int kt = 0; kt < 4; kt++) {
        if (kt < 3) { issue_stage(kt + 1, (kt + 1) & 1); CP_WAIT(1); }
        else        { CP_WAIT(0); }
        __syncthreads();
        uint32_t buf = sb + (kt & 1) * PG_STAGE;

#pragma unroll
        for (int kc = 0; kc < 4; kc++) {
            uint32_t ah[2][4], al[2][4], bh[2][4], bl[2][4];
#pragma unroll
            for (int mh = 0; mh < 2; mh++) {
                int arow = wm * 32 + mh * 16 + la_row;
                uint32_t sw = (((2 * kc + la_sel) ^ (arow & 7)) << 4);
                ldsm4(ah[mh], buf + arow * 128 + sw);
                ldsm4(al[mh], buf + 16384 + arow * 128 + sw);
            }
#pragma unroll
            for (int n16 = 0; n16 < 2; n16++) {
                int brow = wn * 32 + n16 * 16 + lb_row;
                uint32_t sw = (((2 * kc + lb_sel) ^ (brow & 7)) << 4);
                ldsm4(bh[n16], buf + 32768 + brow * 128 + sw);
                ldsm4(bl[n16], buf + 32768 + 8192 + brow * 128 + sw);
            }
#pragma unroll
            for (int mh = 0; mh < 2; mh++)
#pragma unroll
                for (int n16 = 0; n16 < 2; n16++)
#pragma unroll
                    for (int j = 0; j < 2; j++) {
                        float* dd = d[mh][n16 * 2 + j];
                        mma_f16(dd, ah[mh], bh[n16][2 * j], bh[n16][2 * j + 1]);
                        mma_f16(dd, ah[mh], bl[n16][2 * j], bl[n16][2 * j + 1]);
                        mma_f16(dd, al[mh], bh[n16][2 * j], bh[n16][2 * j + 1]);
                    }
        }
        __syncthreads();
    }

    if (blockIdx.x == 0) {
        // ---- f/g epilogue: hi/lo split layout ----
#pragma unroll
        for (int mh = 0; mh < 2; mh++) {
            const long mrow0 = m0 + wm * 32 + mh * 16 + (lane >> 2);
            const long mrow1 = mrow0 + 8;
#pragma unroll
            for (int n16 = 0; n16 < 2; n16++)
#pragma unroll
                for (int j = 0; j < 2; j++) {
                    const float* dd = d[mh][n16 * 2 + j];
                    int col = wn * 32 + n16 * 16 + j * 8 + (lane & 3) * 2;
                    float b0 = sbias[col], b1 = sbias[col + 1];
                    float v00 = dd[0] + b0, v01 = dd[1] + b1;
                    float v10 = dd[2] + b0, v11 = dd[3] + b1;
                    __half* dst = (col < 32) ? fsh : gsh;
                    int c = col & 31;
                    __half2 h0 = __floats2half2_rn(v00, v01);
                    float2 f0 = __half22float2(h0);
                    __half2 l0 = __floats2half2_rn(v00 - f0.x, v01 - f0.y);
                    *(__half2*)(dst + mrow0 * 64 + c) = h0;
                    *(__half2*)(dst + mrow0 * 64 + 32 + c) = l0;
                    __half2 h1 = __floats2half2_rn(v10, v11);
                    float2 f1 = __half22float2(h1);
                    __half2 l1 = __floats2half2_rn(v10 - f1.x, v11 - f1.y);
                    *(__half2*)(dst + mrow1 * 64 + c) = h1;
                    *(__half2*)(dst + mrow1 * 64 + 32 + c) = l1;
                }
        }
    } else {
        // ---- h epilogue: transpose via smem, write ht[B,C,N] coalesced ----
        __half* sT = (__half*)smem;            // [64 ch][136 stride]
#pragma unroll
        for (int mh = 0; mh < 2; mh++) {
            const int r0 = wm * 32 + mh * 16 + (lane >> 2);
            const int r1 = r0 + 8;
#pragma unroll
            for (int n16 = 0; n16 < 2; n16++)
#pragma unroll
                for (int j = 0; j < 2; j++) {
                    const float* dd = d[mh][n16 * 2 + j];
                    int col = wn * 32 + n16 * 16 + j * 8 + (lane & 3) * 2;
                    float b0 = sbias[col], b1 = sbias[col + 1];
                    sT[col * 136 + r0]       = __float2half_rn(dd[0] + b0);
                    sT[(col + 1) * 136 + r0] = __float2half_rn(dd[1] + b1);
                    sT[col * 136 + r1]       = __float2half_rn(dd[2] + b0);
                    sT[(col + 1) * 136 + r1] = __float2half_rn(dd[3] + b1);
                }
        }
        __syncthreads();
        const int b = m0 >> 12;                // m0 / N_
        const int noff = m0 & (N_ - 1);
        const int ch = tid >> 2, q = tid & 3;
        uint4* dst = (uint4*)(ht + ((long)b * C_ + (n0 - 64) + ch) * N_ + noff + q * 32);
        const uint4* srcp = (const uint4*)(sT + ch * 136 + q * 32);
#pragma unroll
        for (int i = 0; i < 4; i++) dst[i] = srcp[i];
    }
}

// ---------------------------------------------------------------------------
// Attention: block = 128 q-rows x batch. 8 warps, one m16 row-slice each.
// Round-7 ordering (MMA1 -> softmax -> MMA2 per tile; phi/sv die in-loop).
// Softmax in log2 domain (G pre-scaled by log2e) -> raw ex2.
// 3-stage cp.async ring (136 KB).
// ---------------------------------------------------------------------------
#define OFF_SG     0
#define STAGE_SZ   (8192 + 32768)
#define OFF_SF(s)  (16384 + (s) * STAGE_SZ)
#define OFF_SH(s)  (16384 + (s) * STAGE_SZ + 8192)
#define SMEM_TOTAL (16384 + 3 * STAGE_SZ)    // 136 KB

__global__ __launch_bounds__(256, 1) void attn_mma(
    const uint4* __restrict__ fsplit, const uint4* __restrict__ gsplit,
    const uint4* __restrict__ ht4,
    const float* __restrict__ x, const float* __restrict__ gamma, float* __restrict__ y)
{
    extern __shared__ char smem[];
    const uint32_t sb = smem_u32(smem);
    const int tid = threadIdx.x, lane = tid & 31, wid = tid >> 5;
    const int b = blockIdx.y, q0 = blockIdx.x * 128;

    const int la_row = (((lane >> 3) & 1) << 3) | (lane & 7);
    const int la_sel = lane >> 4;
    const int lb_row = ((lane >> 4) << 3) | (lane & 7);
    const int lb_sel = (lane >> 3) & 1;

    const int hr = tid >> 3, hc = tid & 7;
    const long hbase = (long)b * C_ * (N_ / 8);
    const long fbase = (long)b * N_ * 8;

    auto stage_attn = [&](int t) {
        const int sn = t % 3;
#pragma unroll
        for (int i = 0; i < 2; i++) {
            int idx = tid + i * 256;
            int r = idx >> 3, c = idx & 7;
            cp16(sb + OFF_SF(sn) + r * 128 + (((c) ^ (r & 7)) << 4),
                 fsplit + fbase + (long)(t * 64 + r) * 8 + c);
        }
#pragma unroll
        for (int i = 0; i < 8; i++) {
            int r = hr + i * 32;
            cp16(sb + OFF_SH(sn) + r * 128 + (((hc) ^ (r & 7)) << 4),
                 ht4 + hbase + (long)r * (N_ / 8) + t * 8 + hc);
        }
        CP_COMMIT();
    };

    // ---- load G tile [128 rows x 128B], swizzled ----
#pragma unroll
    for (int i = 0; i < 4; i++) {
        int idx = tid + i * 256;
        int r = idx >> 3, c = idx & 7;
        uint4 v = gsplit[(long)(b * N_ + q0 + r) * 8 + c];
        *(uint4*)(smem + OFF_SG + r * 128 + (((c) ^ (r & 7)) << 4)) = v;
    }

    // ---- prologue: issue stages 0 and 1 ----
    stage_attn(0);
    stage_attn(1);

    // ---- hoist G A-fragments (constant over tiles) ----
    __syncthreads();
    uint32_t gh[2][4], gl[2][4];
    {
        int row = wid * 16 + la_row;
        uint32_t rowoff = sb + OFF_SG + row * 128;
#pragma unroll
        for (int kc = 0; kc < 2; kc++) {
            ldsm4(gh[kc], rowoff + ((((2 * kc) + la_sel) ^ (row & 7)) << 4));
            ldsm4(gl[kc], rowoff + ((((4 + 2 * kc) + la_sel) ^ (row & 7)) << 4));
        }
    }

    float o[32][4];
#pragma unroll
    for (int i = 0; i < 32; i++)
#pragma unroll
        for (int j = 0; j < 4; j++) o[i][j] = 0.f;
    float lsum0 = 0.f, lsum1 = 0.f;
    float mrun0 = -CUDART_INF_F, mrun1 = -CUDART_INF_F;

#pragma unroll 1
    for (int t = 0; t < NT_; t++) {
        const int s = t % 3;
        CP_WAIT(1);
        __syncthreads();

        // ---- MMA1(t): S[16x64] in log2 domain, 3-term ----
        float sv[8][4];
#pragma unroll
        for (int i = 0; i < 8; i++)
#pragma unroll
            for (int j = 0; j < 4; j++) sv[i][j] = 0.f;

        {
            const uint32_t sfb = sb + OFF_SF(s);
#pragma unroll
            for (int n16 = 0; n16 < 4; n16++) {
                int row = n16 * 16 + lb_row;
                uint32_t rowoff = sfb + row * 128;
                uint32_t fh0[4], fh1[4], fl0[4], fl1[4];
                ldsm4(fh0, rowoff + (((0 + lb_sel) ^ (row & 7)) << 4));
                ldsm4(fh1, rowoff + (((2 + lb_sel) ^ (row & 7)) << 4));
                ldsm4(fl0, rowoff + (((4 + lb_sel) ^ (row & 7)) << 4));
                ldsm4(fl1, rowoff + (((6 + lb_sel) ^ (row & 7)) << 4));
#pragma unroll
                for (int j = 0; j < 2; j++) {
                    float* sd = sv[n16 * 2 + j];
                    mma_f16(sd, gh[0], fh0[2 * j], fh0[2 * j + 1]);
                    mma_f16(sd, gh[1], fh1[2 * j], fh1[2 * j + 1]);
                    mma_f16(sd, gh[0], fl0[2 * j], fl0[2 * j + 1]);
                    mma_f16(sd, gh[1], fl1[2 * j], fl1[2 * j + 1]);
                    mma_f16(sd, gl[0], fh0[2 * j], fh0[2 * j + 1]);
                    mma_f16(sd, gl[1], fh1[2 * j], fh1[2 * j + 1]);
                }
            }
        }

        // ---- softmax(t): per-tile row max + FA2 rescale + exp2 pack ----
        float mt0 = -CUDART_INF_F, mt1 = -CUDART_INF_F;
#pragma unroll
        for (int i = 0; i < 8; i++) {
            mt0 = fmaxf(mt0, fmaxf(sv[i][0], sv[i][1]));
            mt1 = fmaxf(mt1, fmaxf(sv[i][2], sv[i][3]));
        }
        mt0 = fmaxf(mt0, __shfl_xor_sync(0xFFFFFFFFu, mt0, 1));
        mt0 = fmaxf(mt0, __shfl_xor_sync(0xFFFFFFFFu, mt0, 2));
        mt1 = fmaxf(mt1, __shfl_xor_sync(0xFFFFFFFFu, mt1, 1));
        mt1 = fmaxf(mt1, __shfl_xor_sync(0xFFFFFFFFu, mt1, 2));

        const float mn0 = fmaxf(mrun0, mt0);
        const float mn1 = fmaxf(mrun1, mt1);
        const float a0 = ex2(mrun0 - mn0);   // 0 on first tile
        const float a1 = ex2(mrun1 - mn1);
        mrun0 = mn0; mrun1 = mn1;
        lsum0 *= a0; lsum1 *= a1;
        if (a0 != 1.f) {
#pragma unroll
            for (int i = 0; i < 32; i++) { o[i][0] *= a0; o[i][1] *= a0; }
        }
        if (a1 != 1.f) {
#pragma unroll
            for (int i = 0; i < 32; i++) { o[i][2] *= a1; o[i][3] *= a1; }
        }

        uint32_t phi[16];
#pragma unroll
        for (int kc = 0; kc < 4; kc++) {
#pragma unroll
            for (int half = 0; half < 2; half++) {
                float* sd = sv[2 * kc + half];
                float p0 = ex2(sd[0] - mn0);
                float p1 = ex2(sd[1] - mn0);
                float p2 = ex2(sd[2] - mn1);
                float p3 = ex2(sd[3] - mn1);
                lsum0 += p0 + p1;
                lsum1 += p2 + p3;
                __half2 h01 = __floats2half2_rn(p0, p1);
                __half2 h23 = __floats2half2_rn(p2, p3);
                phi[kc * 4 + half * 2 + 0] = *(uint32_t*)&h01;
                phi[kc * 4 + half * 2 + 1] = *(uint32_t*)&h23;
            }
        }

        // ---- MMA2(t): O[16x256] += P.Ht ----
        {
            const uint32_t shb = sb + OFF_SH(s);
#pragma unroll
            for (int n16 = 0; n16 < 16; n16++) {
                int row = n16 * 16 + lb_row;
                uint32_t rhoff = shb + row * 128;
#pragma unroll
                for (int kc = 0; kc < 4; kc++) {
                    uint32_t bh[4];
                    ldsm4(bh, rhoff + ((((2 * kc) + lb_sel) ^ (row & 7)) << 4));
#pragma unroll
                    for (int j = 0; j < 2; j++)
                        mma_f16(o[n16 * 2 + j], &phi[kc * 4], bh[2 * j], bh[2 * j + 1]);
                }
            }
        }

        // ---- issue stage t+2 (slot (t+2)%3 last read at iter t-1) ----
        if (t + 2 < NT_) stage_attn(t + 2);
        else CP_COMMIT();
    }

    // ---- reduce l over the 4 lanes sharing a row ----
    lsum0 += __shfl_xor_sync(0xFFFFFFFFu, lsum0, 1);
    lsum0 += __shfl_xor_sync(0xFFFFFFFFu, lsum0, 2);
    lsum1 += __shfl_xor_sync(0xFFFFFFFFu, lsum1, 1);
    lsum1 += __shfl_xor_sync(0xFFFFFFFFu, lsum1, 2);
    const float inv0 = 1.f / lsum0, inv1 = 1.f / lsum1;
    const float gam = gamma[0];

    // ---- epilogue: y = gamma * O/l + x ----
    const long row0g = ((long)b * N_ + q0 + wid * 16 + (lane >> 2)) * C_;
    const long row1g = row0g + 8 * C_;
#pragma unroll
    for (int n16 = 0; n16 < 16; n16++) {
#pragma unroll
        for (int j = 0; j < 2; j++) {
            const float* od = o[n16 * 2 + j];
            int ch = n16 * 16 + j * 8 + (lane & 3) * 2;
            float2 xv = *(const float2*)(x + row0g + ch);
            float2 yv;
            yv.x = fmaf(gam, od[0] * inv0, xv.x);
            yv.y = fmaf(gam, od[1] * inv0, xv.y);
            *(float2*)(y + row0g + ch) = yv;
            xv = *(const float2*)(x + row1g + ch);
            yv.x = fmaf(gam, od[2] * inv1, xv.x);
            yv.y = fmaf(gam, od[3] * inv1, xv.y);
            *(float2*)(y + row1g + ch) = yv;
        }
    }
}

// ---------------------------------------------------------------------------
extern "C" void kernel_launch(void* const* d_in, const int* in_sizes, int n_in,
                              void* d_out, int out_size)
{
    const float* x     = (const float*)d_in[0];
    const float* Wf    = (const float*)d_in[1];
    const float* bf    = (const float*)d_in[2];
    const float* Wg    = (const float*)d_in[3];
    const float* bg    = (const float*)d_in[4];
    const float* Wh    = (const float*)d_in[5];
    const float* bh    = (const float*)d_in[6];
    const float* gamma = (const float*)d_in[7];
    float* y = (float*)d_out;

    void *xs, *wt, *pb, *fs, *gs, *ht;
    cudaGetSymbolAddress(&xs, g_xs);
    cudaGetSymbolAddress(&wt, g_wt);
    cudaGetSymbolAddress(&pb, g_pb);
    cudaGetSymbolAddress(&fs, g_fs);
    cudaGetSymbolAddress(&gs, g_gs);
    cudaGetSymbolAddress(&ht, g_ht);

    const int M = B_ * N_;

    prep_x<<<M * 32 / 256, 256>>>(x, (uint4*)xs);
    prep_w<<<NP_, 256>>>(Wf, Wg, Wh, bf, bg, bh, (__half*)wt, (float*)pb);

    cudaFuncSetAttribute(proj_mma, cudaFuncAttributeMaxDynamicSharedMemorySize, PG_SMEM);
    proj_mma<<<dim3(NP_ / 64, M / 128), 256, PG_SMEM>>>(
        (const uint4*)xs, (const uint4*)wt, (const float*)pb,
        (__half*)fs, (__half*)gs, (__half*)ht);

    cudaFuncSetAttribute(attn_mma, cudaFuncAttributeMaxDynamicSharedMemorySize, SMEM_TOTAL);
    attn_mma<<<dim3(N_ / 128, B_), 256, SMEM_TOTAL>>>(
        (const uint4*)fs, (const uint4*)gs, (const uint4*)ht, x, gamma, y);
}